// round 16
// baseline (speedup 1.0000x reference)
#include <cuda_runtime.h>
#include <cuda_fp16.h>

// Problem shapes (fixed by setup_inputs)
#define BN 64
#define VN 64
#define DN 64
#define HN 64
#define EN 4032     // V*(V-1)
#define ETN 2
#define OUTC (DN + HN)   // 128
#define GY 13            // batch groups (grid.y)
#define NBLK (32 * GY)   // 416 blocks <= 444 = 3/SM * 148 SM capacity

// Node-factored first layer, stored FP16 (computed in phase A):
//   g_Ah[b][v][h] = fp16( b1[1][h] + sum_d in[b][v][d]*W1[1][h][d] )
//   g_Bh[b][v][h] = fp16(            sum_d in[b][v][d]*W1[1][h][DN+d] )
__device__ __half g_Ah[BN * VN * HN];
__device__ __half g_Bh[BN * VN * HN];
// W2[1] pre-packed into m16n8k16 A-fragment layout (block 0, phase A)
__device__ unsigned g_W2frag[2 * 32 * 4 * 8];
// Device-wide barrier counter. Each launch adds exactly NBLK, so the
// per-launch target (t/NBLK+1)*NBLK is self-consistent across graph
// replays with NO reset needed.
__device__ unsigned long long g_bar;

__device__ __forceinline__ void cp16(unsigned dst_smem, const void* src) {
    asm volatile("cp.async.ca.shared.global [%0], [%1], 16;"
                 :: "r"(dst_smem), "l"(src));
}
__device__ __forceinline__ unsigned hadd2u(unsigned a, unsigned b) {
    __half2 r = __hadd2(*reinterpret_cast<__half2*>(&a),
                        *reinterpret_cast<__half2*>(&b));
    return *reinterpret_cast<unsigned*>(&r);
}
__device__ __forceinline__ unsigned relu2u(unsigned a) {
    __half2 z = __half2half2(__ushort_as_half(0));
    __half2 r = __hmax2(*reinterpret_cast<__half2*>(&a), z);
    return *reinterpret_cast<unsigned*>(&r);
}
__device__ __forceinline__ unsigned packh2(float lo, float hi) {
    __half2 h = __floats2half2_rn(lo, hi);
    return *reinterpret_cast<unsigned*>(&h);
}

// ---------------------------------------------------------------------------
// Fused kernel: phase A (node-table precompute slice) -> device barrier ->
// phase B (fp16 m16n8k16 edge MLP, R15 machinery).
// Grid 32 x 13 = 416 blocks, 3/SM -> all co-resident (spin barrier safe).
// smem: phase A's W1 staging (34816B) unions with phase B's buffers (29952B).
// ---------------------------------------------------------------------------
__device__ __forceinline__ void stage_batch(unsigned bhA, unsigned ahA,
                                            int bufIdx, int batch,
                                            int tid, int rbase) {
    const __half* src = g_Bh + (size_t)batch * VN * HN;
    unsigned dstB = bhA + bufIdx * 8192;
    #pragma unroll
    for (int t = 0; t < 2; t++) {
        int c = tid + t * 256;            // chunk id 0..511
        int s = c >> 3, q = c & 7;
        int slot = q ^ (s & 7);
        cp16(dstB + s * 128 + slot * 16, src + c * 8);
    }
    if (tid < 16)
        cp16(ahA + bufIdx * 256 + tid * 16,
             g_Ah + ((size_t)(batch * VN + rbase)) * HN + tid * 8);
    asm volatile("cp.async.commit_group;");
}

__global__ __launch_bounds__(256, 3)
void fused_gnn_kernel(const float* __restrict__ inputs,
                      const float* __restrict__ edges,
                      const float* __restrict__ W1,
                      const float* __restrict__ b1,
                      const float* __restrict__ W2,
                      const float* __restrict__ b2,
                      float* __restrict__ out) {
    // Union region: phase A = W1r/W1s [64][68] fp32 each (34816 B);
    // phase B = Bh[3][4096]h + Ah[3][128]h + wva[640]f + P[512]f (29952 B).
    __shared__ __align__(16) char smem_u[34816];
    float* W1r = (float*)smem_u;                    // [d][h] pitch 68
    float* W1s = W1r + 64 * 68;
    __half* Bh  = (__half*)smem_u;                  // 3 x 4096 halfs
    __half* Ah  = (__half*)(smem_u + 24576);        // 3 x 128 halfs
    float*  wva = (float*)(smem_u + 25344);         // 5 x 128 floats
    float*  P   = (float*)(smem_u + 27904);         // 2 x 256 floats

    int tid   = threadIdx.x;
    int bid   = blockIdx.y * 32 + blockIdx.x;
    int s0    = (blockIdx.y * BN) / GY;
    int nb    = ((blockIdx.y + 1) * BN) / GY - s0;
    int rbase = blockIdx.x * 2;

    // ======================= PHASE A: precompute slice ====================
    // Stage W1[1] transposed into smem
    {
        const float* W1e = W1 + HN * 2 * DN;  // edge type 1
        for (int idx = tid; idx < HN * 2 * DN; idx += 256) {
            int h = idx >> 7, d = idx & 127;
            float w = W1e[idx];
            if (d < DN) W1r[d * 68 + h] = w;
            else        W1s[(d - DN) * 68 + h] = w;
        }
    }
    // Block 0: pack W2[1] fragments
    if (bid == 0) {
        const float* W2e = W2 + HN * HN;   // [o][k]
        int ohp  = tid >> 7;
        int lp   = (tid >> 2) & 31;
        int msp  = tid & 3;
        int gidp = lp >> 2, ctidp = lp & 3;
        int r0   = ohp * 32 + gidp;
        int p    = ctidp * 16 + msp * 4;
        uint4 qa, qb;
        qa.x = packh2(W2e[r0 * 64 + p],           W2e[r0 * 64 + p + 1]);
        qa.y = packh2(W2e[(r0 + 8) * 64 + p],     W2e[(r0 + 8) * 64 + p + 1]);
        qa.z = packh2(W2e[r0 * 64 + p + 2],       W2e[r0 * 64 + p + 3]);
        qa.w = packh2(W2e[(r0 + 8) * 64 + p + 2], W2e[(r0 + 8) * 64 + p + 3]);
        qb.x = packh2(W2e[(r0 + 16) * 64 + p],        W2e[(r0 + 16) * 64 + p + 1]);
        qb.y = packh2(W2e[(r0 + 24) * 64 + p],        W2e[(r0 + 24) * 64 + p + 1]);
        qb.z = packh2(W2e[(r0 + 16) * 64 + p + 2],    W2e[(r0 + 16) * 64 + p + 3]);
        qb.w = packh2(W2e[(r0 + 24) * 64 + p + 2],    W2e[(r0 + 24) * 64 + p + 3]);
        uint4* Wf4 = reinterpret_cast<uint4*>(g_W2frag);
        Wf4[tid * 2]     = qa;
        Wf4[tid * 2 + 1] = qb;
    }
    __syncthreads();

    // This block's node rows: [bid*128/13, (bid+1)*128/13) of 4096
    {
        int r0g = (bid * 128) / GY;
        int r1g = ((bid + 1) * 128) / GY;
        int ty  = tid >> 4;           // candidate row offset
        int tx  = tid & 15;           // h quad
        int row = r0g + ty;
        if (row < r1g) {
            const float* xr = inputs + (size_t)row * DN;
            float acc1[4] = {0.f, 0.f, 0.f, 0.f};
            float acc2[4] = {0.f, 0.f, 0.f, 0.f};
            #pragma unroll 8
            for (int d = 0; d < DN; d++) {
                float xv = xr[d];
                float4 wr = *(const float4*)&W1r[d * 68 + 4 * tx];
                float4 ws = *(const float4*)&W1s[d * 68 + 4 * tx];
                acc1[0] += xv * wr.x;  acc1[1] += xv * wr.y;
                acc1[2] += xv * wr.z;  acc1[3] += xv * wr.w;
                acc2[0] += xv * ws.x;  acc2[1] += xv * ws.y;
                acc2[2] += xv * ws.z;  acc2[3] += xv * ws.w;
            }
            __half2 pa0 = __floats2half2_rn(acc1[0] + b1[HN + 4 * tx],
                                            acc1[1] + b1[HN + 4 * tx + 1]);
            __half2 pa1 = __floats2half2_rn(acc1[2] + b1[HN + 4 * tx + 2],
                                            acc1[3] + b1[HN + 4 * tx + 3]);
            __half2 pb0 = __floats2half2_rn(acc2[0], acc2[1]);
            __half2 pb1 = __floats2half2_rn(acc2[2], acc2[3]);
            size_t base = (size_t)row * HN + 4 * tx;
            uint2 ua, ub;
            ua.x = *reinterpret_cast<unsigned*>(&pa0);
            ua.y = *reinterpret_cast<unsigned*>(&pa1);
            ub.x = *reinterpret_cast<unsigned*>(&pb0);
            ub.y = *reinterpret_cast<unsigned*>(&pb1);
            *reinterpret_cast<uint2*>(&g_Ah[base]) = ua;
            *reinterpret_cast<uint2*>(&g_Bh[base]) = ub;
        }
    }

    // ======================= DEVICE-WIDE BARRIER ==========================
    __syncthreads();                  // all phase-A stores issued
    if (tid == 0) {
        __threadfence();              // visible at GPU scope
        unsigned long long t = atomicAdd(&g_bar, 1ULL);
        unsigned long long target = (t / NBLK + 1ULL) * NBLK;
        unsigned long long v;
        do {
            asm volatile("ld.acquire.gpu.u64 %0, [%1];"
                         : "=l"(v) : "l"(&g_bar));
        } while (v < target);
    }
    __syncthreads();                  // whole block past barrier

    // ======================= PHASE B: edge MLP ============================
    int w     = tid >> 5;
    int l     = tid & 31;
    int gid   = l >> 2;
    int ctid  = l & 3;
    int oh    = w & 1;
    int sh    = (w >> 1) & 1;
    int rl    = w >> 2;
    int obase = oh * 32;

    unsigned bhA = (unsigned)__cvta_generic_to_shared(Bh);
    unsigned ahA = (unsigned)__cvta_generic_to_shared(Ah);

    // Prefetch depth 2 (nb >= 4 always)
    stage_batch(bhA, ahA, 0, s0,     tid, rbase);
    stage_batch(bhA, ahA, 1, s0 + 1, tid, rbase);

    // W2 A-fragments: 8 coalesced LDG.128 from pre-packed g_W2frag
    unsigned a0f[4][4], a1f[4][4];
    float bias[2][2];
    {
        const uint4* Wf4 = reinterpret_cast<const uint4*>(g_W2frag);
        int fbase = ((oh * 32 + l) * 4) * 2;
        #pragma unroll
        for (int ms = 0; ms < 4; ms++) {
            uint4 qa = Wf4[fbase + ms * 2];
            uint4 qb = Wf4[fbase + ms * 2 + 1];
            a0f[ms][0] = qa.x; a0f[ms][1] = qa.y;
            a0f[ms][2] = qa.z; a0f[ms][3] = qa.w;
            a1f[ms][0] = qb.x; a1f[ms][1] = qb.y;
            a1f[ms][2] = qb.z; a1f[ms][3] = qb.w;
        }
        bias[0][0] = b2[HN + obase + gid];
        bias[0][1] = b2[HN + obase + 8 + gid];
        bias[1][0] = b2[HN + obase + 16 + gid];
        bias[1][1] = b2[HN + obase + 24 + gid];
    }

    // Edge weights for nb batches (closed-form e(s,r) = s*63 + r - (r>s))
    for (int idx = tid; idx < nb * 128; idx += 256) {
        int bi = idx >> 7, row = idx & 127;
        int srl = row >> 6, s = row & 63;
        int r = rbase + srl;
        float wgt = 0.f;
        if (s != r) {
            int e = s * 63 + r - (r > s ? 1 : 0);
            wgt = edges[((size_t)((s0 + bi) * EN + e)) * ETN + 1];
        }
        wva[idx] = wgt;
    }

    int buf = 0;   // = bi % 3
    for (int bi = 0; bi < nb; bi++) {
        if (bi == nb - 1) asm volatile("cp.async.wait_group 0;");
        else              asm volatile("cp.async.wait_group 1;");
        __syncthreads();
        // batch s0+bi in Bh[buf]/Ah[buf]; wva visible; P[(bi-1)&1] complete.

        // Store previous batch's agg output + inputs copy
        if (bi > 0 && tid < 128) {
            int srl = tid >> 6, o = tid & 63;
            int bprev = s0 + bi - 1;
            size_t row = (size_t)(bprev * VN + rbase + srl);
            const float* Pp = P + ((bi - 1) & 1) * 256 + srl * 128;
            out[row * OUTC + DN + o] = Pp[o] + Pp[64 + o];
            out[row * OUTC + o]      = inputs[row * DN + o];
        }

        // Prefetch batch bi+2
        if (bi + 2 < nb) {
            int nxt = buf + 2; if (nxt >= 3) nxt -= 3;
            stage_batch(bhA, ahA, nxt, s0 + bi + 2, tid, rbase);
        }

        // A cache: 16 halfs (phys k run) = 2x LDS.128 broadcast
        unsigned aa[8];
        {
            const __half* Ar = Ah + buf * 128 + rl * 64 + ctid * 16;
            uint4 la0 = *(const uint4*)&Ar[0];
            uint4 la1 = *(const uint4*)&Ar[8];
            aa[0] = la0.x; aa[1] = la0.y; aa[2] = la0.z; aa[3] = la0.w;
            aa[4] = la1.x; aa[5] = la1.y; aa[6] = la1.z; aa[7] = la1.w;
        }

        float pa[2][2] = {{0.f, 0.f}, {0.f, 0.f}};
        const float* wvb = wva + bi * 128 + rl * 64;
        #pragma unroll
        for (int j = 0; j < 4; j++) {
            int nt = sh * 4 + j;
            int s  = nt * 8 + gid;
            const __half* srow = Bh + buf * 4096 + s * 64;
            int c0 = (2 * ctid)     ^ (s & 7);
            int c1 = (2 * ctid + 1) ^ (s & 7);
            uint4 lb0 = *(const uint4*)&srow[c0 * 8];
            uint4 lb1 = *(const uint4*)&srow[c1 * 8];
            unsigned bb[8] = {lb0.x, lb0.y, lb0.z, lb0.w,
                              lb1.x, lb1.y, lb1.z, lb1.w};

            float c0a[4] = {0.f, 0.f, 0.f, 0.f};
            float c1a[4] = {0.f, 0.f, 0.f, 0.f};
            #pragma unroll
            for (int ms = 0; ms < 4; ms++) {
                unsigned ub0 = relu2u(hadd2u(aa[2 * ms],     bb[2 * ms]));
                unsigned ub1 = relu2u(hadd2u(aa[2 * ms + 1], bb[2 * ms + 1]));
                asm volatile(
                    "mma.sync.aligned.m16n8k16.row.col.f32.f16.f16.f32 "
                    "{%0,%1,%2,%3}, {%4,%5,%6,%7}, {%8,%9}, {%0,%1,%2,%3};"
                    : "+f"(c0a[0]), "+f"(c0a[1]), "+f"(c0a[2]), "+f"(c0a[3])
                    : "r"(a0f[ms][0]), "r"(a0f[ms][1]),
                      "r"(a0f[ms][2]), "r"(a0f[ms][3]),
                      "r"(ub0), "r"(ub1));
                asm volatile(
                    "mma.sync.aligned.m16n8k16.row.col.f32.f16.f16.f32 "
                    "{%0,%1,%2,%3}, {%4,%5,%6,%7}, {%8,%9}, {%0,%1,%2,%3};"
                    : "+f"(c1a[0]), "+f"(c1a[1]), "+f"(c1a[2]), "+f"(c1a[3])
                    : "r"(a1f[ms][0]), "r"(a1f[ms][1]),
                      "r"(a1f[ms][2]), "r"(a1f[ms][3]),
                      "r"(ub0), "r"(ub1));
            }
            int scol = nt * 8 + 2 * ctid;
            float w0 = wvb[scol], w1 = wvb[scol + 1];
            pa[0][0] += w0 * fmaxf(c0a[0] + bias[0][0], 0.f)
                      + w1 * fmaxf(c0a[1] + bias[0][0], 0.f);
            pa[0][1] += w0 * fmaxf(c0a[2] + bias[0][1], 0.f)
                      + w1 * fmaxf(c0a[3] + bias[0][1], 0.f);
            pa[1][0] += w0 * fmaxf(c1a[0] + bias[1][0], 0.f)
                      + w1 * fmaxf(c1a[1] + bias[1][0], 0.f);
            pa[1][1] += w0 * fmaxf(c1a[2] + bias[1][1], 0.f)
                      + w1 * fmaxf(c1a[3] + bias[1][1], 0.f);
        }
        // Reduce over the 4 sender-pair lane-groups
        #pragma unroll
        for (int ot = 0; ot < 2; ot++)
            #pragma unroll
            for (int hf = 0; hf < 2; hf++) {
                pa[ot][hf] += __shfl_xor_sync(0xFFFFFFFFu, pa[ot][hf], 1);
                pa[ot][hf] += __shfl_xor_sync(0xFFFFFFFFu, pa[ot][hf], 2);
            }
        if (ctid == 0) {
            float* Pp = P + (bi & 1) * 256 + rl * 128 + sh * 64 + obase;
            Pp[gid]      = pa[0][0];
            Pp[gid + 8]  = pa[0][1];
            Pp[gid + 16] = pa[1][0];
            Pp[gid + 24] = pa[1][1];
        }
        buf = (buf == 2) ? 0 : buf + 1;
    }
    __syncthreads();
    // Final batch's stores
    if (tid < 128) {
        int srl = tid >> 6, o = tid & 63;
        int blast = s0 + nb - 1;
        size_t row = (size_t)(blast * VN + rbase + srl);
        const float* Pp = P + ((nb - 1) & 1) * 256 + srl * 128;
        out[row * OUTC + DN + o] = Pp[o] + Pp[64 + o];
        out[row * OUTC + o]      = inputs[row * DN + o];
    }
}

// ---------------------------------------------------------------------------
// Launch: ONE kernel.
// ---------------------------------------------------------------------------
extern "C" void kernel_launch(void* const* d_in, const int* in_sizes, int n_in,
                              void* d_out, int out_size) {
    const float* inputs = (const float*)d_in[0];
    const float* edges  = (const float*)d_in[1];
    const float* W1     = (const float*)d_in[2];
    const float* b1     = (const float*)d_in[3];
    const float* W2     = (const float*)d_in[4];
    const float* b2     = (const float*)d_in[5];
    float* out = (float*)d_out;

    dim3 grid(VN / 2, GY);   // 32 x 13 = 416 blocks, all co-resident
    fused_gnn_kernel<<<grid, 256>>>(inputs, edges, W1, b1, W2, b2, out);
}

// round 17
// speedup vs baseline: 1.2266x; 1.2266x over previous
#include <cuda_runtime.h>
#include <cuda_fp16.h>

// Problem shapes (fixed by setup_inputs)
#define BN 64
#define VN 64
#define DN 64
#define HN 64
#define EN 4032     // V*(V-1)
#define ETN 2
#define OUTC (DN + HN)   // 128
#define GY 13            // batch groups (grid.y): 416 blocks <= 444 capacity

// Node-factored first layer, stored FP16:
//   g_Ah[row][h] = fp16( b1[1][h] + sum_d X[row][d]*W1[1][h][d] )
//   g_Bh[row][h] = fp16(            sum_d X[row][d]*W1[1][h][DN+d] )
// (row = b*VN + v, flattened)
__device__ __half g_Ah[BN * VN * HN];
__device__ __half g_Bh[BN * VN * HN];
// W2[1] pre-packed into m16n8k16 A-fragment layout
__device__ unsigned g_W2frag[2 * 32 * 4 * 8];

__device__ __forceinline__ void cp16(unsigned dst_smem, const void* src) {
    asm volatile("cp.async.ca.shared.global [%0], [%1], 16;"
                 :: "r"(dst_smem), "l"(src));
}
__device__ __forceinline__ unsigned hadd2u(unsigned a, unsigned b) {
    __half2 r = __hadd2(*reinterpret_cast<__half2*>(&a),
                        *reinterpret_cast<__half2*>(&b));
    return *reinterpret_cast<unsigned*>(&r);
}
__device__ __forceinline__ unsigned relu2u(unsigned a) {
    __half2 z = __half2half2(__ushort_as_half(0));
    __half2 r = __hmax2(*reinterpret_cast<__half2*>(&a), z);
    return *reinterpret_cast<unsigned*>(&r);
}
__device__ __forceinline__ unsigned packh2(float lo, float hi) {
    __half2 h = __floats2half2_rn(lo, hi);
    return *reinterpret_cast<unsigned*>(&h);
}

// ---------------------------------------------------------------------------
// Kernel 1: TENSOR-CORE layer-1 precompute.
// C_A[16 rows, 64 h] = X[16,64] @ W1[1][:, 0:64]^T   (+ b1[1])
// C_B[16 rows, 64 h] = X[16,64] @ W1[1][:, 64:128]^T
// Grid 256 blocks (16 rows each) x 256 threads (8 warps).
// Warp w: halfsel = w&1 (A/B), hbase = (w>>1)*16 (one m16 h-tile), both
// n-tiles (16 rows). Fragment maps mirror the verified edge-kernel
// convention: phys k p = ctid*16 + ms*4; A regs {(h,p:p+1),(h+8,p:p+1),
// (h,p+2:p+3),(h+8,p+2:p+3)}; B regs {(row,p:p+1),(row,p+2:p+3)};
// C c0..c3 = (h,2ctid),(h,2ctid+1),(h+8,2ctid),(h+8,2ctid+1).
// Results transposed through smem -> coalesced 16B stores.
// Block 0 also packs W2[1] into g_W2frag.
// ---------------------------------------------------------------------------
__global__ __launch_bounds__(256)
void precompute_mma_kernel(const float* __restrict__ inp,
                           const float* __restrict__ W1,
                           const float* __restrict__ b1,
                           const float* __restrict__ W2) {
    __shared__ __align__(16) __half Ct[16 * 136];  // [16 rows][128 cols + 8 pad]

    int tid  = threadIdx.x;
    int bid  = blockIdx.x;
    int r0   = bid * 16;            // first node-row of this block
    int w    = tid >> 5;
    int l    = tid & 31;
    int gid  = l >> 2;
    int ctid = l & 3;
    int halfsel = w & 1;            // 0 = A-half (d 0..63), 1 = B-half
    int hbase   = (w >> 1) * 16;

    // Block 0: pack W2[1] fragments (independent work)
    if (bid == 0) {
        const float* W2e = W2 + HN * HN;   // [o][k]
        int ohp  = tid >> 7;
        int lp   = (tid >> 2) & 31;
        int msp  = tid & 3;
        int gidp = lp >> 2, ctidp = lp & 3;
        int rr   = ohp * 32 + gidp;
        int p    = ctidp * 16 + msp * 4;
        uint4 qa, qb;
        qa.x = packh2(W2e[rr * 64 + p],           W2e[rr * 64 + p + 1]);
        qa.y = packh2(W2e[(rr + 8) * 64 + p],     W2e[(rr + 8) * 64 + p + 1]);
        qa.z = packh2(W2e[rr * 64 + p + 2],       W2e[rr * 64 + p + 3]);
        qa.w = packh2(W2e[(rr + 8) * 64 + p + 2], W2e[(rr + 8) * 64 + p + 3]);
        qb.x = packh2(W2e[(rr + 16) * 64 + p],        W2e[(rr + 16) * 64 + p + 1]);
        qb.y = packh2(W2e[(rr + 24) * 64 + p],        W2e[(rr + 24) * 64 + p + 1]);
        qb.z = packh2(W2e[(rr + 16) * 64 + p + 2],    W2e[(rr + 16) * 64 + p + 3]);
        qb.w = packh2(W2e[(rr + 24) * 64 + p + 2],    W2e[(rr + 24) * 64 + p + 3]);
        uint4* Wf4 = reinterpret_cast<uint4*>(g_W2frag);
        Wf4[tid * 2]     = qa;
        Wf4[tid * 2 + 1] = qb;
    }

    // --- W1 A-fragments (fp16) for this warp's (halfsel, h-tile) ---
    const float* W1e = W1 + HN * 2 * DN;   // W1[1], [h 64][d2 128]
    int doff = halfsel * 64;
    unsigned af[4][4];
    {
        int hA = hbase + gid;
        #pragma unroll
        for (int ms = 0; ms < 4; ms++) {
            int p = ctid * 16 + ms * 4;
            float4 w0 = *(const float4*)&W1e[hA * 128 + doff + p];
            float4 w8 = *(const float4*)&W1e[(hA + 8) * 128 + doff + p];
            af[ms][0] = packh2(w0.x, w0.y);
            af[ms][1] = packh2(w8.x, w8.y);
            af[ms][2] = packh2(w0.z, w0.w);
            af[ms][3] = packh2(w8.z, w8.w);
        }
    }
    // --- X B-fragments (fp16) for both n-tiles ---
    unsigned bf[2][4][2];
    {
        #pragma unroll
        for (int nt = 0; nt < 2; nt++) {
            int row = r0 + nt * 8 + gid;
            const float* xr = inp + (size_t)row * DN;
            #pragma unroll
            for (int ms = 0; ms < 4; ms++) {
                int p = ctid * 16 + ms * 4;
                float4 xv = *(const float4*)&xr[p];
                bf[nt][ms][0] = packh2(xv.x, xv.y);
                bf[nt][ms][1] = packh2(xv.z, xv.w);
            }
        }
    }
    // Bias (A-half only)
    float bias0 = 0.f, bias1 = 0.f;
    if (halfsel == 0) {
        bias0 = b1[HN + hbase + gid];
        bias1 = b1[HN + hbase + 8 + gid];
    }

    // --- mma + transpose-store to smem ---
    #pragma unroll
    for (int nt = 0; nt < 2; nt++) {
        float c0 = 0.f, c1 = 0.f, c2 = 0.f, c3 = 0.f;
        #pragma unroll
        for (int ms = 0; ms < 4; ms++) {
            asm volatile(
                "mma.sync.aligned.m16n8k16.row.col.f32.f16.f16.f32 "
                "{%0,%1,%2,%3}, {%4,%5,%6,%7}, {%8,%9}, {%0,%1,%2,%3};"
                : "+f"(c0), "+f"(c1), "+f"(c2), "+f"(c3)
                : "r"(af[ms][0]), "r"(af[ms][1]), "r"(af[ms][2]), "r"(af[ms][3]),
                  "r"(bf[nt][ms][0]), "r"(bf[nt][ms][1]));
        }
        int rloc = nt * 8 + 2 * ctid;       // local rows rloc, rloc+1
        int col  = halfsel * 64 + hbase + gid;
        Ct[rloc * 136 + col]           = __float2half_rn(c0 + bias0);
        Ct[(rloc + 1) * 136 + col]     = __float2half_rn(c1 + bias0);
        Ct[rloc * 136 + col + 8]       = __float2half_rn(c2 + bias1);
        Ct[(rloc + 1) * 136 + col + 8] = __float2half_rn(c3 + bias1);
    }
    __syncthreads();

    // --- Coalesced copy smem -> g_Ah / g_Bh (one 16B chunk per thread) ---
    {
        int rowl = tid >> 4;          // 0..15
        int seg  = tid & 15;          // 16B segment within the 128-half row
        uint4 v = *(const uint4*)&Ct[rowl * 136 + seg * 8];
        size_t grow = (size_t)(r0 + rowl) * HN;
        if (seg < 8)
            *reinterpret_cast<uint4*>(&g_Ah[grow + seg * 8]) = v;
        else
            *reinterpret_cast<uint4*>(&g_Bh[grow + (seg - 8) * 8]) = v;
    }
}

// ---------------------------------------------------------------------------
// Kernel 2: all-fp16 m16n8k16 transposed-GEMM edge MLP (R15, unchanged).
// ---------------------------------------------------------------------------
__device__ __forceinline__ void stage_batch(unsigned bhA, unsigned ahA,
                                            int bufIdx, int batch,
                                            int tid, int rbase) {
    const __half* src = g_Bh + (size_t)batch * VN * HN;
    unsigned dstB = bhA + bufIdx * 8192;
    #pragma unroll
    for (int t = 0; t < 2; t++) {
        int c = tid + t * 256;            // chunk id 0..511
        int s = c >> 3, q = c & 7;
        int slot = q ^ (s & 7);
        cp16(dstB + s * 128 + slot * 16, src + c * 8);
    }
    if (tid < 16)
        cp16(ahA + bufIdx * 256 + tid * 16,
             g_Ah + ((size_t)(batch * VN + rbase)) * HN + tid * 8);
    asm volatile("cp.async.commit_group;");
}

__global__ __launch_bounds__(256, 3)
void edge_mma_kernel(const float* __restrict__ inputs,
                     const float* __restrict__ edges,
                     const float* __restrict__ b2,
                     float* __restrict__ out) {
    __shared__ __align__(16) __half Bh[3][4096];   // 3 x [64 rows][64 halfs], swizzled
    __shared__ __align__(16) __half Ah[3][128];    // 3 x [2 recv][64 halfs]
    __shared__ float wva[5 * 128];                 // edge weights, up to 5 batches
    __shared__ float P[2 * 256];                   // double-buffered sender partials

    int s0    = (blockIdx.y * BN) / GY;            // first batch
    int nb    = ((blockIdx.y + 1) * BN) / GY - s0; // 4 or 5 batches
    int rbase = blockIdx.x * 2;
    int tid   = threadIdx.x;
    int w     = tid >> 5;
    int l     = tid & 31;
    int gid   = l >> 2;
    int ctid  = l & 3;
    int oh    = w & 1;
    int sh    = (w >> 1) & 1;
    int rl    = w >> 2;
    int obase = oh * 32;

    unsigned bhA = (unsigned)__cvta_generic_to_shared(&Bh[0][0]);
    unsigned ahA = (unsigned)__cvta_generic_to_shared(&Ah[0][0]);

    // Prefetch depth 2 (nb >= 4 always)
    stage_batch(bhA, ahA, 0, s0,     tid, rbase);
    stage_batch(bhA, ahA, 1, s0 + 1, tid, rbase);

    // W2 A-fragments: 8 coalesced LDG.128 from pre-packed g_W2frag
    unsigned a0f[4][4], a1f[4][4];
    float bias[2][2];
    {
        const uint4* Wf4 = reinterpret_cast<const uint4*>(g_W2frag);
        int fbase = ((oh * 32 + l) * 4) * 2;
        #pragma unroll
        for (int ms = 0; ms < 4; ms++) {
            uint4 qa = Wf4[fbase + ms * 2];
            uint4 qb = Wf4[fbase + ms * 2 + 1];
            a0f[ms][0] = qa.x; a0f[ms][1] = qa.y;
            a0f[ms][2] = qa.z; a0f[ms][3] = qa.w;
            a1f[ms][0] = qb.x; a1f[ms][1] = qb.y;
            a1f[ms][2] = qb.z; a1f[ms][3] = qb.w;
        }
        bias[0][0] = b2[HN + obase + gid];
        bias[0][1] = b2[HN + obase + 8 + gid];
        bias[1][0] = b2[HN + obase + 16 + gid];
        bias[1][1] = b2[HN + obase + 24 + gid];
    }

    // Edge weights for nb batches (closed-form e(s,r) = s*63 + r - (r>s))
    for (int idx = tid; idx < nb * 128; idx += 256) {
        int bi = idx >> 7, row = idx & 127;
        int srl = row >> 6, s = row & 63;
        int r = rbase + srl;
        float wgt = 0.f;
        if (s != r) {
            int e = s * 63 + r - (r > s ? 1 : 0);
            wgt = edges[((size_t)((s0 + bi) * EN + e)) * ETN + 1];
        }
        wva[idx] = wgt;
    }

    int buf = 0;   // = bi % 3
    for (int bi = 0; bi < nb; bi++) {
        if (bi == nb - 1) asm volatile("cp.async.wait_group 0;");
        else              asm volatile("cp.async.wait_group 1;");
        __syncthreads();

        // Store previous batch's agg output + inputs copy
        if (bi > 0 && tid < 128) {
            int srl = tid >> 6, o = tid & 63;
            int bprev = s0 + bi - 1;
            size_t row = (size_t)(bprev * VN + rbase + srl);
            const float* Pp = P + ((bi - 1) & 1) * 256 + srl * 128;
            out[row * OUTC + DN + o] = Pp[o] + Pp[64 + o];
            out[row * OUTC + o]      = inputs[row * DN + o];
        }

        // Prefetch batch bi+2
        if (bi + 2 < nb) {
            int nxt = buf + 2; if (nxt >= 3) nxt -= 3;
            stage_batch(bhA, ahA, nxt, s0 + bi + 2, tid, rbase);
        }

        // A cache: 16 halfs (phys k run) = 2x LDS.128 broadcast
        unsigned aa[8];
        {
            const __half* Ar = Ah[buf] + rl * 64 + ctid * 16;
            uint4 la0 = *(const uint4*)&Ar[0];
            uint4 la1 = *(const uint4*)&Ar[8];
            aa[0] = la0.x; aa[1] = la0.y; aa[2] = la0.z; aa[3] = la0.w;
            aa[4] = la1.x; aa[5] = la1.y; aa[6] = la1.z; aa[7] = la1.w;
        }

        float pa[2][2] = {{0.f, 0.f}, {0.f, 0.f}};
        const float* wvb = wva + bi * 128 + rl * 64;
        #pragma unroll
        for (int j = 0; j < 4; j++) {
            int nt = sh * 4 + j;
            int s  = nt * 8 + gid;
            const __half* srow = Bh[buf] + s * 64;
            int c0 = (2 * ctid)     ^ (s & 7);
            int c1 = (2 * ctid + 1) ^ (s & 7);
            uint4 lb0 = *(const uint4*)&srow[c0 * 8];
            uint4 lb1 = *(const uint4*)&srow[c1 * 8];
            unsigned bb[8] = {lb0.x, lb0.y, lb0.z, lb0.w,
                              lb1.x, lb1.y, lb1.z, lb1.w};

            float c0a[4] = {0.f, 0.f, 0.f, 0.f};
            float c1a[4] = {0.f, 0.f, 0.f, 0.f};
            #pragma unroll
            for (int ms = 0; ms < 4; ms++) {
                unsigned ub0 = relu2u(hadd2u(aa[2 * ms],     bb[2 * ms]));
                unsigned ub1 = relu2u(hadd2u(aa[2 * ms + 1], bb[2 * ms + 1]));
                asm volatile(
                    "mma.sync.aligned.m16n8k16.row.col.f32.f16.f16.f32 "
                    "{%0,%1,%2,%3}, {%4,%5,%6,%7}, {%8,%9}, {%0,%1,%2,%3};"
                    : "+f"(c0a[0]), "+f"(c0a[1]), "+f"(c0a[2]), "+f"(c0a[3])
                    : "r"(a0f[ms][0]), "r"(a0f[ms][1]),
                      "r"(a0f[ms][2]), "r"(a0f[ms][3]),
                      "r"(ub0), "r"(ub1));
                asm volatile(
                    "mma.sync.aligned.m16n8k16.row.col.f32.f16.f16.f32 "
                    "{%0,%1,%2,%3}, {%4,%5,%6,%7}, {%8,%9}, {%0,%1,%2,%3};"
                    : "+f"(c1a[0]), "+f"(c1a[1]), "+f"(c1a[2]), "+f"(c1a[3])
                    : "r"(a1f[ms][0]), "r"(a1f[ms][1]),
                      "r"(a1f[ms][2]), "r"(a1f[ms][3]),
                      "r"(ub0), "r"(ub1));
            }
            int scol = nt * 8 + 2 * ctid;
            float w0 = wvb[scol], w1 = wvb[scol + 1];
            pa[0][0] += w0 * fmaxf(c0a[0] + bias[0][0], 0.f)
                      + w1 * fmaxf(c0a[1] + bias[0][0], 0.f);
            pa[0][1] += w0 * fmaxf(c0a[2] + bias[0][1], 0.f)
                      + w1 * fmaxf(c0a[3] + bias[0][1], 0.f);
            pa[1][0] += w0 * fmaxf(c1a[0] + bias[1][0], 0.f)
                      + w1 * fmaxf(c1a[1] + bias[1][0], 0.f);
            pa[1][1] += w0 * fmaxf(c1a[2] + bias[1][1], 0.f)
                      + w1 * fmaxf(c1a[3] + bias[1][1], 0.f);
        }
        // Reduce over the 4 sender-pair lane-groups
        #pragma unroll
        for (int ot = 0; ot < 2; ot++)
            #pragma unroll
            for (int hf = 0; hf < 2; hf++) {
                pa[ot][hf] += __shfl_xor_sync(0xFFFFFFFFu, pa[ot][hf], 1);
                pa[ot][hf] += __shfl_xor_sync(0xFFFFFFFFu, pa[ot][hf], 2);
            }
        if (ctid == 0) {
            float* Pp = P + (bi & 1) * 256 + rl * 128 + sh * 64 + obase;
            Pp[gid]      = pa[0][0];
            Pp[gid + 8]  = pa[0][1];
            Pp[gid + 16] = pa[1][0];
            Pp[gid + 24] = pa[1][1];
        }
        buf = (buf == 2) ? 0 : buf + 1;
    }
    __syncthreads();
    // Final batch's stores
    if (tid < 128) {
        int srl = tid >> 6, o = tid & 63;
        int blast = s0 + nb - 1;
        size_t row = (size_t)(blast * VN + rbase + srl);
        const float* Pp = P + ((nb - 1) & 1) * 256 + srl * 128;
        out[row * OUTC + DN + o] = Pp[o] + Pp[64 + o];
        out[row * OUTC + o]      = inputs[row * DN + o];
    }
}

// ---------------------------------------------------------------------------
// Launch
// ---------------------------------------------------------------------------
extern "C" void kernel_launch(void* const* d_in, const int* in_sizes, int n_in,
                              void* d_out, int out_size) {
    const float* inputs = (const float*)d_in[0];
    const float* edges  = (const float*)d_in[1];
    const float* W1     = (const float*)d_in[2];
    const float* b1     = (const float*)d_in[3];
    const float* W2     = (const float*)d_in[4];
    const float* b2     = (const float*)d_in[5];
    float* out = (float*)d_out;

    // 1: tensor-core layer-1 precompute (+ W2 frag pack)
    precompute_mma_kernel<<<256, 256>>>(inputs, W1, b1, W2);

    // 2: edge MLP (R15, unchanged)
    {
        dim3 grid(VN / 2, GY);   // 32 x 13 = 416 blocks, single wave
        edge_mma_kernel<<<grid, 256>>>(inputs, edges, b2, out);
    }
}